// round 3
// baseline (speedup 1.0000x reference)
#include <cuda_runtime.h>
#include <math.h>

#define N_TOK 8192
#define C_DIM 1024
#define H_DIM 4096
#define E_NUM 8

// ---- scratch (static device globals; no runtime allocation allowed) ----
__device__ float g_xg[(size_t)N_TOK * C_DIM];   // gathered x, grouped by expert (33.5 MB)
__device__ float g_h[(size_t)N_TOK * H_DIM];    // hidden activations (134 MB)
__device__ int   g_idx[N_TOK];
__device__ float g_prob[N_TOK];
__device__ int   g_perm[N_TOK];                 // grouped position -> token id
__device__ int   g_counts[E_NUM];
__device__ int   g_offsets[E_NUM + 1];
__device__ int   g_fill[E_NUM];

// ---------------------------------------------------------------- zero
__global__ void zero_kernel() {
    int t = threadIdx.x;
    if (t < E_NUM) { g_counts[t] = 0; g_fill[t] = 0; }
}

// ---------------------------------------------------------------- router
// One block per token: logits = x[token] @ Wr + br ; softmax ; top-1.
__global__ __launch_bounds__(128) void router_kernel(const float* __restrict__ x,
                                                     const float* __restrict__ Wr,
                                                     const float* __restrict__ br) {
    int token = blockIdx.x;
    int tid = threadIdx.x;
    const float* xr = x + (size_t)token * C_DIM;

    float acc[E_NUM];
#pragma unroll
    for (int e = 0; e < E_NUM; e++) acc[e] = 0.f;

    for (int c = tid; c < C_DIM; c += 128) {
        float xv = xr[c];
        const float* w = Wr + c * E_NUM;
#pragma unroll
        for (int e = 0; e < E_NUM; e++) acc[e] += xv * w[e];
    }

    __shared__ float sred[128];
    __shared__ float logits[E_NUM];
    for (int e = 0; e < E_NUM; e++) {
        sred[tid] = acc[e];
        __syncthreads();
        for (int s = 64; s > 0; s >>= 1) {
            if (tid < s) sred[tid] += sred[tid + s];
            __syncthreads();
        }
        if (tid == 0) logits[e] = sred[0] + br[e];
        __syncthreads();
    }

    if (tid == 0) {
        float lmax = logits[0];
        int best = 0;
#pragma unroll
        for (int e = 1; e < E_NUM; e++)
            if (logits[e] > lmax) { lmax = logits[e]; best = e; }
        float sum = 0.f;
#pragma unroll
        for (int e = 0; e < E_NUM; e++) sum += expf(logits[e] - lmax);
        g_idx[token] = best;
        g_prob[token] = 1.f / sum;   // = exp(lmax-lmax)/sum = top-1 gate
        atomicAdd(&g_counts[best], 1);
    }
}

// ---------------------------------------------------------------- scan + aux
__global__ void scan_kernel(float* __restrict__ out, int out_size) {
    if (threadIdx.x == 0 && blockIdx.x == 0) {
        int acc = 0;
        for (int e = 0; e < E_NUM; e++) { g_offsets[e] = acc; acc += g_counts[e]; }
        g_offsets[E_NUM] = acc;
        if (out_size > N_TOK * C_DIM) {
            float total = fmaxf((float)acc, 1.f);
            float aux = 0.f;
            for (int e = 0; e < E_NUM; e++) {
                float f = (float)g_counts[e] / total - (1.f / E_NUM);
                aux += f * f;
            }
            out[(size_t)N_TOK * C_DIM] = aux / E_NUM;
        }
    }
}

// ---------------------------------------------------------------- perm build
__global__ void perm_kernel() {
    int t = blockIdx.x * blockDim.x + threadIdx.x;
    if (t < N_TOK) {
        int e = g_idx[t];
        int pos = g_offsets[e] + atomicAdd(&g_fill[e], 1);
        g_perm[pos] = t;
    }
}

// ---------------------------------------------------------------- gather rows
__global__ __launch_bounds__(256) void gather_kernel(const float* __restrict__ x) {
    int p = blockIdx.x;           // grouped row
    int token = g_perm[p];
    const float4* src = (const float4*)(x + (size_t)token * C_DIM);
    float4* dst = (float4*)(g_xg + (size_t)p * C_DIM);
    dst[threadIdx.x] = src[threadIdx.x];   // 256 * float4 = 1024 floats
}

// ---------------------------------------------------------------- grouped GEMM
// 128x128 tile, 256 threads, 8x8 per-thread microtile, BK=8.
// IS_FFN1:  g_h[row] = gelu(g_xg[row] @ W1[e] + b1[e])
// !IS_FFN1: out[token] = prob[token] * (g_h[row] @ W2[e] + b2[e])  (scatter)
template <int KDIM, int NDIM, bool IS_FFN1>
__global__ __launch_bounds__(256) void gemm_kernel(const float* __restrict__ W,
                                                   const float* __restrict__ bias,
                                                   float* __restrict__ out) {
    int e = blockIdx.z;
    int row0 = g_offsets[e];
    int cnt = g_offsets[e + 1] - row0;
    int mbase = blockIdx.y * 128;
    if (mbase >= cnt) return;
    int nbase = blockIdx.x * 128;

    const float* A = (IS_FFN1 ? g_xg : g_h) + (size_t)row0 * KDIM;
    const float* B = W + (size_t)e * KDIM * NDIM;

    __shared__ float As[8][128];
    __shared__ float Bs[8][128];

    int tid = threadIdx.x;
    int tx = tid & 15, ty = tid >> 4;
    int am = tid >> 1, ak = (tid & 1) * 4;       // A tile: 128 rows x 8 k
    int bk = tid >> 5, bn = (tid & 31) * 4;      // B tile: 8 k x 128 n

    float acc[8][8];
#pragma unroll
    for (int i = 0; i < 8; i++)
#pragma unroll
        for (int j = 0; j < 8; j++) acc[i][j] = 0.f;

    bool avalid = (mbase + am) < cnt;
    const float* Aptr = A + (size_t)(mbase + am) * KDIM + ak;
    const float* Bptr = B + (size_t)bk * NDIM + nbase + bn;

    for (int k0 = 0; k0 < KDIM; k0 += 8) {
        float4 av = avalid ? *(const float4*)(Aptr + k0)
                           : make_float4(0.f, 0.f, 0.f, 0.f);
        As[ak + 0][am] = av.x;
        As[ak + 1][am] = av.y;
        As[ak + 2][am] = av.z;
        As[ak + 3][am] = av.w;

        float4 bv = *(const float4*)(Bptr + (size_t)k0 * NDIM);
        *(float4*)&Bs[bk][bn] = bv;

        __syncthreads();
#pragma unroll
        for (int k = 0; k < 8; k++) {
            float a[8], b[8];
#pragma unroll
            for (int i = 0; i < 8; i++) a[i] = As[k][ty * 8 + i];
#pragma unroll
            for (int j = 0; j < 8; j++) b[j] = Bs[k][tx * 8 + j];
#pragma unroll
            for (int i = 0; i < 8; i++)
#pragma unroll
                for (int j = 0; j < 8; j++)
                    acc[i][j] = fmaf(a[i], b[j], acc[i][j]);
        }
        __syncthreads();
    }

    if (IS_FFN1) {
#pragma unroll
        for (int i = 0; i < 8; i++) {
            int m = mbase + ty * 8 + i;
            if (m < cnt) {
                float* hrow = g_h + (size_t)(row0 + m) * NDIM + nbase + tx * 8;
                const float* brow = bias + e * NDIM + nbase + tx * 8;
#pragma unroll
                for (int j = 0; j < 8; j++) {
                    float v = acc[i][j] + brow[j];
                    v = 0.5f * v * (1.f + erff(v * 0.70710678118654752f));
                    hrow[j] = v;
                }
            }
        }
    } else {
#pragma unroll
        for (int i = 0; i < 8; i++) {
            int m = mbase + ty * 8 + i;
            if (m < cnt) {
                int token = g_perm[row0 + m];
                float p = g_prob[token];
                float* orow = out + (size_t)token * NDIM + nbase + tx * 8;
                const float* brow = bias + e * NDIM + nbase + tx * 8;
#pragma unroll
                for (int j = 0; j < 8; j++)
                    orow[j] = p * (acc[i][j] + brow[j]);
            }
        }
    }
}

// ---------------------------------------------------------------- launch
extern "C" void kernel_launch(void* const* d_in, const int* in_sizes, int n_in,
                              void* d_out, int out_size) {
    const float* x  = (const float*)d_in[0];
    const float* Wr = (const float*)d_in[1];
    const float* br = (const float*)d_in[2];
    const float* W1 = (const float*)d_in[3];
    const float* b1 = (const float*)d_in[4];
    const float* W2 = (const float*)d_in[5];
    const float* b2 = (const float*)d_in[6];
    float* out = (float*)d_out;

    zero_kernel<<<1, 32>>>();
    router_kernel<<<N_TOK, 128>>>(x, Wr, br);
    scan_kernel<<<1, 32>>>(out, out_size);
    perm_kernel<<<(N_TOK + 255) / 256, 256>>>();
    gather_kernel<<<N_TOK, 256>>>(x);

    dim3 g1(H_DIM / 128, (N_TOK + 127) / 128, E_NUM);
    gemm_kernel<C_DIM, H_DIM, true><<<g1, 256>>>(W1, b1, nullptr);

    dim3 g2(C_DIM / 128, (N_TOK + 127) / 128, E_NUM);
    gemm_kernel<H_DIM, C_DIM, false><<<g2, 256>>>(W2, b2, out);
}

// round 5
// speedup vs baseline: 1.0007x; 1.0007x over previous
#include <cuda_runtime.h>
#include <math.h>

#define N_TOK 8192
#define C_DIM 1024
#define H_DIM 4096
#define E_NUM 8

// ---- scratch (static device globals; no runtime allocation allowed) ----
__device__ float g_xg[(size_t)N_TOK * C_DIM];   // gathered x, grouped by expert (33.5 MB)
__device__ float g_h[(size_t)N_TOK * H_DIM];    // hidden activations (134 MB)
__device__ int   g_idx[N_TOK];
__device__ float g_prob[N_TOK];
__device__ int   g_perm[N_TOK];                 // grouped position -> token id
__device__ int   g_counts[E_NUM];
__device__ int   g_offsets[E_NUM + 1];
__device__ int   g_fill[E_NUM];

// ---------------------------------------------------------------- zero
__global__ void zero_kernel() {
    int t = threadIdx.x;
    if (t < E_NUM) { g_counts[t] = 0; g_fill[t] = 0; }
}

// ---------------------------------------------------------------- router
// One block per token: logits = x[token] @ Wr + br ; softmax ; top-1.
__global__ __launch_bounds__(128) void router_kernel(const float* __restrict__ x,
                                                     const float* __restrict__ Wr,
                                                     const float* __restrict__ br) {
    int token = blockIdx.x;
    int tid = threadIdx.x;
    const float* xr = x + (size_t)token * C_DIM;

    float acc[E_NUM];
#pragma unroll
    for (int e = 0; e < E_NUM; e++) acc[e] = 0.f;

    for (int c = tid; c < C_DIM; c += 128) {
        float xv = xr[c];
        const float* w = Wr + c * E_NUM;
#pragma unroll
        for (int e = 0; e < E_NUM; e++) acc[e] += xv * w[e];
    }

    __shared__ float sred[128];
    __shared__ float logits[E_NUM];
    for (int e = 0; e < E_NUM; e++) {
        sred[tid] = acc[e];
        __syncthreads();
        for (int s = 64; s > 0; s >>= 1) {
            if (tid < s) sred[tid] += sred[tid + s];
            __syncthreads();
        }
        if (tid == 0) logits[e] = sred[0] + br[e];
        __syncthreads();
    }

    if (tid == 0) {
        float lmax = logits[0];
        int best = 0;
#pragma unroll
        for (int e = 1; e < E_NUM; e++)
            if (logits[e] > lmax) { lmax = logits[e]; best = e; }
        float sum = 0.f;
#pragma unroll
        for (int e = 0; e < E_NUM; e++) sum += expf(logits[e] - lmax);
        g_idx[token] = best;
        g_prob[token] = 1.f / sum;   // = exp(lmax-lmax)/sum = top-1 gate
        atomicAdd(&g_counts[best], 1);
    }
}

// ---------------------------------------------------------------- scan + aux
__global__ void scan_kernel(float* __restrict__ out, int out_size) {
    if (threadIdx.x == 0 && blockIdx.x == 0) {
        int acc = 0;
        for (int e = 0; e < E_NUM; e++) { g_offsets[e] = acc; acc += g_counts[e]; }
        g_offsets[E_NUM] = acc;
        if (out_size > N_TOK * C_DIM) {
            float total = fmaxf((float)acc, 1.f);
            float aux = 0.f;
            for (int e = 0; e < E_NUM; e++) {
                float f = (float)g_counts[e] / total - (1.f / E_NUM);
                aux += f * f;
            }
            out[(size_t)N_TOK * C_DIM] = aux / E_NUM;
        }
    }
}

// ---------------------------------------------------------------- perm build
__global__ void perm_kernel() {
    int t = blockIdx.x * blockDim.x + threadIdx.x;
    if (t < N_TOK) {
        int e = g_idx[t];
        int pos = g_offsets[e] + atomicAdd(&g_fill[e], 1);
        g_perm[pos] = t;
    }
}

// ---------------------------------------------------------------- gather rows
__global__ __launch_bounds__(256) void gather_kernel(const float* __restrict__ x) {
    int p = blockIdx.x;           // grouped row
    int token = g_perm[p];
    const float4* src = (const float4*)(x + (size_t)token * C_DIM);
    float4* dst = (float4*)(g_xg + (size_t)p * C_DIM);
    dst[threadIdx.x] = src[threadIdx.x];   // 256 * float4 = 1024 floats
}

// ---------------------------------------------------------------- grouped GEMM
// 128x128 tile, 256 threads, 8x8 per-thread microtile, BK=8.
// IS_FFN1:  g_h[row] = gelu(g_xg[row] @ W1[e] + b1[e])
// !IS_FFN1: out[token] = prob[token] * (g_h[row] @ W2[e] + b2[e])  (scatter)
template <int KDIM, int NDIM, bool IS_FFN1>
__global__ __launch_bounds__(256) void gemm_kernel(const float* __restrict__ W,
                                                   const float* __restrict__ bias,
                                                   float* __restrict__ out) {
    int e = blockIdx.z;
    int row0 = g_offsets[e];
    int cnt = g_offsets[e + 1] - row0;
    int mbase = blockIdx.y * 128;
    if (mbase >= cnt) return;
    int nbase = blockIdx.x * 128;

    const float* A = (IS_FFN1 ? g_xg : g_h) + (size_t)row0 * KDIM;
    const float* B = W + (size_t)e * KDIM * NDIM;

    __shared__ float As[8][128];
    __shared__ float Bs[8][128];

    int tid = threadIdx.x;
    int tx = tid & 15, ty = tid >> 4;
    int am = tid >> 1, ak = (tid & 1) * 4;       // A tile: 128 rows x 8 k
    int bk = tid >> 5, bn = (tid & 31) * 4;      // B tile: 8 k x 128 n

    float acc[8][8];
#pragma unroll
    for (int i = 0; i < 8; i++)
#pragma unroll
        for (int j = 0; j < 8; j++) acc[i][j] = 0.f;

    bool avalid = (mbase + am) < cnt;
    const float* Aptr = A + (size_t)(mbase + am) * KDIM + ak;
    const float* Bptr = B + (size_t)bk * NDIM + nbase + bn;

    for (int k0 = 0; k0 < KDIM; k0 += 8) {
        float4 av = avalid ? *(const float4*)(Aptr + k0)
                           : make_float4(0.f, 0.f, 0.f, 0.f);
        As[ak + 0][am] = av.x;
        As[ak + 1][am] = av.y;
        As[ak + 2][am] = av.z;
        As[ak + 3][am] = av.w;

        float4 bv = *(const float4*)(Bptr + (size_t)k0 * NDIM);
        *(float4*)&Bs[bk][bn] = bv;

        __syncthreads();
#pragma unroll
        for (int k = 0; k < 8; k++) {
            float a[8], b[8];
#pragma unroll
            for (int i = 0; i < 8; i++) a[i] = As[k][ty * 8 + i];
#pragma unroll
            for (int j = 0; j < 8; j++) b[j] = Bs[k][tx * 8 + j];
#pragma unroll
            for (int i = 0; i < 8; i++)
#pragma unroll
                for (int j = 0; j < 8; j++)
                    acc[i][j] = fmaf(a[i], b[j], acc[i][j]);
        }
        __syncthreads();
    }

    if (IS_FFN1) {
#pragma unroll
        for (int i = 0; i < 8; i++) {
            int m = mbase + ty * 8 + i;
            if (m < cnt) {
                float* hrow = g_h + (size_t)(row0 + m) * NDIM + nbase + tx * 8;
                const float* brow = bias + e * NDIM + nbase + tx * 8;
#pragma unroll
                for (int j = 0; j < 8; j++) {
                    float v = acc[i][j] + brow[j];
                    v = 0.5f * v * (1.f + erff(v * 0.70710678118654752f));
                    hrow[j] = v;
                }
            }
        }
    } else {
#pragma unroll
        for (int i = 0; i < 8; i++) {
            int m = mbase + ty * 8 + i;
            if (m < cnt) {
                int token = g_perm[row0 + m];
                float p = g_prob[token];
                float* orow = out + (size_t)token * NDIM + nbase + tx * 8;
                const float* brow = bias + e * NDIM + nbase + tx * 8;
#pragma unroll
                for (int j = 0; j < 8; j++)
                    orow[j] = p * (acc[i][j] + brow[j]);
            }
        }
    }
}

// ---------------------------------------------------------------- launch
extern "C" void kernel_launch(void* const* d_in, const int* in_sizes, int n_in,
                              void* d_out, int out_size) {
    const float* x  = (const float*)d_in[0];
    const float* Wr = (const float*)d_in[1];
    const float* br = (const float*)d_in[2];
    const float* W1 = (const float*)d_in[3];
    const float* b1 = (const float*)d_in[4];
    const float* W2 = (const float*)d_in[5];
    const float* b2 = (const float*)d_in[6];
    float* out = (float*)d_out;

    zero_kernel<<<1, 32>>>();
    router_kernel<<<N_TOK, 128>>>(x, Wr, br);
    scan_kernel<<<1, 32>>>(out, out_size);
    perm_kernel<<<(N_TOK + 255) / 256, 256>>>();
    gather_kernel<<<N_TOK, 256>>>(x);

    dim3 g1(H_DIM / 128, (N_TOK + 127) / 128, E_NUM);
    gemm_kernel<C_DIM, H_DIM, true><<<g1, 256>>>(W1, b1, nullptr);

    dim3 g2(C_DIM / 128, (N_TOK + 127) / 128, E_NUM);
    gemm_kernel<H_DIM, C_DIM, false><<<g2, 256>>>(W2, b2, out);
}